// round 1
// baseline (speedup 1.0000x reference)
#include <cuda_runtime.h>
#include <math.h>

#define Bsz 32
#define Nn  1024
#define Dd  128
#define NROWS (Bsz*Nn)

// Scratch (device globals: allocation-free rule)
__device__ float g_itr[NROWS * Dd];   // itr_attn output, 16.8 MB
__device__ float g_qa[NROWS];         // per-token column bias qa[j] = P[j].wa

// ---------------------------------------------------------------------------
// qa kernel: one warp per token row, qa = dot(P[row,:], w[0:128])
// ---------------------------------------------------------------------------
__global__ void qa_kernel(const float* __restrict__ P, const float* __restrict__ w) {
    int row  = blockIdx.x * blockDim.y + threadIdx.y;
    int lane = threadIdx.x;
    if (row >= NROWS) return;
    const float* p = P + (size_t)row * Dd;
    float s = 0.f;
    #pragma unroll
    for (int k = lane; k < Dd; k += 32) s += p[k] * w[k];
    #pragma unroll
    for (int off = 16; off > 0; off >>= 1) s += __shfl_xor_sync(0xffffffffu, s, off);
    if (lane == 0) g_qa[row] = s;
}

// ---------------------------------------------------------------------------
// Flash-attention kernel.
// S[i,j] = (P[i]*wc) . P[j] + qa[j]   (row bias (P@wb)[i] cancels in softmax)
// itr = softmax_j(S) @ P
// Tile: BM=128 query rows x BN=128 keys, D=128. 256 threads (16x16),
// 8x8 register micro-tile; cols strided by 16 for conflict-free smem reads.
// ---------------------------------------------------------------------------
#define BM  128
#define BN  128
#define LDP 132   // padded smem row stride (floats): 132 % 32 == 4 -> 2-way max

__global__ __launch_bounds__(256, 1)
void flash_kernel(const float* __restrict__ P, const float* __restrict__ w) {
    extern __shared__ float sm[];
    float* Qs  = sm;                   // BM*LDP
    float* Ks  = Qs + BM * LDP;        // BN*LDP  (K tile == V tile, since K=V=P)
    float* SAs = Ks + BN * LDP;        // BM*LDP
    float* qas = SAs + BM * LDP;       // BN
    float* ms  = qas + BN;             // BM running max
    float* ls  = ms + BM;              // BM running sum

    const int b   = blockIdx.y;
    const int i0  = blockIdx.x * BM;
    const int tid = threadIdx.x;
    const int tx  = tid & 15;
    const int ty  = tid >> 4;

    // Load Q tile = P[b, i0:i0+BM, :] * wc  (wc = w + 2*D)
    {
        const float4* wc4 = (const float4*)(w + 2 * Dd);
        const float4* Pg  = (const float4*)(P + ((size_t)b * Nn + i0) * Dd);
        #pragma unroll
        for (int t = 0; t < (BM * (Dd / 4)) / 256; t++) {
            int idx = tid + t * 256;
            int r = idx >> 5, c4 = idx & 31;
            float4 v  = Pg[r * (Dd / 4) + c4];
            float4 wv = wc4[c4];
            v.x *= wv.x; v.y *= wv.y; v.z *= wv.z; v.w *= wv.w;
            *(float4*)(Qs + r * LDP + c4 * 4) = v;
        }
    }
    for (int r = tid; r < BM; r += 256) { ms[r] = -1e30f; ls[r] = 0.f; }

    float O[8][8];
    #pragma unroll
    for (int y = 0; y < 8; y++)
        #pragma unroll
        for (int u = 0; u < 8; u++) O[y][u] = 0.f;

    for (int j0 = 0; j0 < Nn; j0 += BN) {
        __syncthreads();  // previous PV done before overwriting K tile
        {
            const float4* Kg = (const float4*)(P + ((size_t)b * Nn + j0) * Dd);
            #pragma unroll
            for (int t = 0; t < (BN * (Dd / 4)) / 256; t++) {
                int idx = tid + t * 256;
                int r = idx >> 5, c4 = idx & 31;
                *(float4*)(Ks + r * LDP + c4 * 4) = Kg[r * (Dd / 4) + c4];
            }
            if (tid < BN) qas[tid] = g_qa[(size_t)b * Nn + j0 + tid];
        }
        __syncthreads();

        // ---- S = Q @ K^T  (rows r=ty*8+y, cols c=tx+16*x) ----
        float S[8][8];
        #pragma unroll
        for (int y = 0; y < 8; y++)
            #pragma unroll
            for (int x = 0; x < 8; x++) S[y][x] = 0.f;

        #pragma unroll 1
        for (int k = 0; k < Dd; k += 4) {
            float4 q[8];
            #pragma unroll
            for (int y = 0; y < 8; y++)
                q[y] = *(const float4*)(Qs + (ty * 8 + y) * LDP + k);
            #pragma unroll
            for (int x = 0; x < 8; x++) {
                float4 kv = *(const float4*)(Ks + (tx + 16 * x) * LDP + k);
                #pragma unroll
                for (int y = 0; y < 8; y++) {
                    S[y][x] += q[y].x * kv.x;
                    S[y][x] += q[y].y * kv.y;
                    S[y][x] += q[y].z * kv.z;
                    S[y][x] += q[y].w * kv.w;
                }
            }
        }

        // ---- online softmax (add column bias qa[j]) ----
        #pragma unroll
        for (int y = 0; y < 8; y++) {
            const int r = ty * 8 + y;
            float mx = -1e30f;
            #pragma unroll
            for (int x = 0; x < 8; x++) {
                S[y][x] += qas[tx + 16 * x];
                mx = fmaxf(mx, S[y][x]);
            }
            #pragma unroll
            for (int off = 1; off < 16; off <<= 1)
                mx = fmaxf(mx, __shfl_xor_sync(0xffffffffu, mx, off));
            float mold  = ms[r];
            float mnew  = fmaxf(mold, mx);
            float alpha = __expf(mold - mnew);
            float ssum  = 0.f;
            #pragma unroll
            for (int x = 0; x < 8; x++) {
                float pv = __expf(S[y][x] - mnew);
                S[y][x] = pv;
                ssum += pv;
            }
            #pragma unroll
            for (int off = 1; off < 16; off <<= 1)
                ssum += __shfl_xor_sync(0xffffffffu, ssum, off);
            if (tx == 0) { ms[r] = mnew; ls[r] = ls[r] * alpha + ssum; }
            #pragma unroll
            for (int u = 0; u < 8; u++) O[y][u] *= alpha;
            #pragma unroll
            for (int x = 0; x < 8; x++)
                SAs[r * LDP + tx + 16 * x] = S[y][x];
        }
        // No cross-warp dependency between softmax and PV: each warp-group
        // reads only its own SA rows, V tile (Ks) is read-only here.

        // ---- O += SA @ V  (V tile == Ks) ----
        #pragma unroll 1
        for (int j = 0; j < BN; j += 4) {
            float4 a[8];
            #pragma unroll
            for (int y = 0; y < 8; y++)
                a[y] = *(const float4*)(SAs + (ty * 8 + y) * LDP + j);
            #pragma unroll
            for (int jj = 0; jj < 4; jj++) {
                float v[8];
                #pragma unroll
                for (int u = 0; u < 8; u++)
                    v[u] = Ks[(j + jj) * LDP + tx + 16 * u];
                #pragma unroll
                for (int y = 0; y < 8; y++) {
                    float av = (jj == 0) ? a[y].x : (jj == 1) ? a[y].y
                             : (jj == 2) ? a[y].z : a[y].w;
                    #pragma unroll
                    for (int u = 0; u < 8; u++) O[y][u] += av * v[u];
                }
            }
        }
    }
    __syncthreads();

    // Normalize and store itr
    #pragma unroll
    for (int y = 0; y < 8; y++) {
        const int r = ty * 8 + y;
        float inv = 1.f / ls[r];
        float* dst = g_itr + ((size_t)b * Nn + i0 + r) * Dd;
        #pragma unroll
        for (int u = 0; u < 8; u++)
            dst[tx + 16 * u] = O[y][u] * inv;
    }
}

// ---------------------------------------------------------------------------
// Fused gated MLP: X = [P, itr] (K=256), three GEMMs to D=128 each + epilogue
// out = sigmoid(X@w2+b2) * P + sigmoid(X@w3+b3) * tanh(X@w1+b1)
// Block: 64 rows x 128 cols, 256 threads, 4x8 micro-tile per weight.
// ---------------------------------------------------------------------------
#define MBM 64
#define LDX 68

__global__ __launch_bounds__(256, 1)
void mlp_kernel(const float* __restrict__ P,
                const float* __restrict__ w1, const float* __restrict__ w2,
                const float* __restrict__ w3,
                const float* __restrict__ b1, const float* __restrict__ b2,
                const float* __restrict__ b3,
                float* __restrict__ out) {
    extern __shared__ float sm[];
    float* Xs  = sm;                 // MBM * LDX
    float* W1s = Xs + MBM * LDX;     // 64 * 128
    float* W2s = W1s + 64 * 128;
    float* W3s = W2s + 64 * 128;

    const int row0 = blockIdx.x * MBM;
    const int tid  = threadIdx.x;
    const int tx   = tid & 15;
    const int ty   = tid >> 4;

    float a1[4][8], a2[4][8], a3[4][8];
    #pragma unroll
    for (int y = 0; y < 4; y++)
        #pragma unroll
        for (int u = 0; u < 8; u++) { a1[y][u] = 0.f; a2[y][u] = 0.f; a3[y][u] = 0.f; }

    for (int kc = 0; kc < 4; kc++) {
        __syncthreads();
        // X chunk: k in [kc*64, kc*64+64). Chunks 0,1 come from P; 2,3 from itr.
        const float* Xbase = (kc < 2)
            ? (P     + (size_t)row0 * Dd + kc * 64)
            : (g_itr + (size_t)row0 * Dd + (kc - 2) * 64);
        #pragma unroll
        for (int t = 0; t < 4; t++) {            // 64 rows * 16 float4 = 1024
            int idx = tid + t * 256;
            int r = idx >> 4, c4 = idx & 15;
            float4 v = *(const float4*)(Xbase + (size_t)r * Dd + c4 * 4);
            *(float4*)(Xs + r * LDX + c4 * 4) = v;
        }
        const float4* w1g = (const float4*)(w1 + (size_t)kc * 64 * Dd);
        const float4* w2g = (const float4*)(w2 + (size_t)kc * 64 * Dd);
        const float4* w3g = (const float4*)(w3 + (size_t)kc * 64 * Dd);
        #pragma unroll
        for (int t = 0; t < 8; t++) {            // 64*128/4 = 2048 float4
            int idx = tid + t * 256;
            ((float4*)W1s)[idx] = w1g[idx];
            ((float4*)W2s)[idx] = w2g[idx];
            ((float4*)W3s)[idx] = w3g[idx];
        }
        __syncthreads();

        #pragma unroll 2
        for (int kk = 0; kk < 64; kk++) {
            float xv[4];
            #pragma unroll
            for (int y = 0; y < 4; y++) xv[y] = Xs[(ty * 4 + y) * LDX + kk];

            float4 wA = *(const float4*)(W1s + kk * 128 + tx * 8);
            float4 wB = *(const float4*)(W1s + kk * 128 + tx * 8 + 4);
            #pragma unroll
            for (int y = 0; y < 4; y++) {
                a1[y][0] += xv[y] * wA.x; a1[y][1] += xv[y] * wA.y;
                a1[y][2] += xv[y] * wA.z; a1[y][3] += xv[y] * wA.w;
                a1[y][4] += xv[y] * wB.x; a1[y][5] += xv[y] * wB.y;
                a1[y][6] += xv[y] * wB.z; a1[y][7] += xv[y] * wB.w;
            }
            wA = *(const float4*)(W2s + kk * 128 + tx * 8);
            wB = *(const float4*)(W2s + kk * 128 + tx * 8 + 4);
            #pragma unroll
            for (int y = 0; y < 4; y++) {
                a2[y][0] += xv[y] * wA.x; a2[y][1] += xv[y] * wA.y;
                a2[y][2] += xv[y] * wA.z; a2[y][3] += xv[y] * wA.w;
                a2[y][4] += xv[y] * wB.x; a2[y][5] += xv[y] * wB.y;
                a2[y][6] += xv[y] * wB.z; a2[y][7] += xv[y] * wB.w;
            }
            wA = *(const float4*)(W3s + kk * 128 + tx * 8);
            wB = *(const float4*)(W3s + kk * 128 + tx * 8 + 4);
            #pragma unroll
            for (int y = 0; y < 4; y++) {
                a3[y][0] += xv[y] * wA.x; a3[y][1] += xv[y] * wA.y;
                a3[y][2] += xv[y] * wA.z; a3[y][3] += xv[y] * wA.w;
                a3[y][4] += xv[y] * wB.x; a3[y][5] += xv[y] * wB.y;
                a3[y][6] += xv[y] * wB.z; a3[y][7] += xv[y] * wB.w;
            }
        }
    }

    // Epilogue: z=tanh(..w1+b1), r=sigmoid(..w2+b2), f=sigmoid(..w3+b3)
    #pragma unroll
    for (int y = 0; y < 4; y++) {
        int r = row0 + ty * 4 + y;
        const float* prow = P + (size_t)r * Dd;
        float* orow = out + (size_t)r * Dd;
        #pragma unroll
        for (int u = 0; u < 8; u++) {
            int c = tx * 8 + u;
            float z  = tanhf(a1[y][u] + b1[c]);
            float rr = 1.f / (1.f + __expf(-(a2[y][u] + b2[c])));
            float ff = 1.f / (1.f + __expf(-(a3[y][u] + b3[c])));
            orow[c] = rr * prow[c] + ff * z;
        }
    }
}

// ---------------------------------------------------------------------------
extern "C" void kernel_launch(void* const* d_in, const int* in_sizes, int n_in,
                              void* d_out, int out_size) {
    const float* P  = (const float*)d_in[0];
    const float* w  = (const float*)d_in[1];
    const float* w1 = (const float*)d_in[2];
    const float* w2 = (const float*)d_in[3];
    const float* w3 = (const float*)d_in[4];
    const float* b1 = (const float*)d_in[5];
    const float* b2 = (const float*)d_in[6];
    const float* b3 = (const float*)d_in[7];
    float* out = (float*)d_out;

    const size_t flash_smem = (size_t)(3 * BM * LDP + BN + 2 * BM) * sizeof(float); // 204288 B
    const size_t mlp_smem   = (size_t)(MBM * LDX + 3 * 64 * 128) * sizeof(float);   // 115712 B
    cudaFuncSetAttribute(flash_kernel, cudaFuncAttributeMaxDynamicSharedMemorySize,
                         (int)flash_smem);
    cudaFuncSetAttribute(mlp_kernel, cudaFuncAttributeMaxDynamicSharedMemorySize,
                         (int)mlp_smem);

    dim3 qb(32, 8);
    qa_kernel<<<NROWS / 8, qb>>>(P, w);

    dim3 fg(Nn / BM, Bsz);
    flash_kernel<<<fg, 256, flash_smem>>>(P, w);

    mlp_kernel<<<NROWS / MBM, 256, mlp_smem>>>(P, w1, w2, w3, b1, b2, b3, out);
}